// round 1
// baseline (speedup 1.0000x reference)
#include <cuda_runtime.h>
#include <cuda_bf16.h>

#define NN 50000
#define NE 600000
#define DD 128
#define NL 6

// Scratch (no allocations allowed): ping-pong h buffers, aggregate, degree.
__device__ float g_h0[NN * DD];
__device__ float g_h1[NN * DD];
__device__ float g_agg[NN * DD];
__device__ float g_deg[NN];

// ---------------------------------------------------------------------------
// degree
// ---------------------------------------------------------------------------
__global__ void zero_deg_kernel() {
    int i = blockIdx.x * blockDim.x + threadIdx.x;
    if (i < NN) g_deg[i] = 0.0f;
}

__global__ void deg_kernel(const int* __restrict__ dst) {
    int e = blockIdx.x * blockDim.x + threadIdx.x;
    if (e < NE) atomicAdd(&g_deg[dst[e]], 1.0f);
}

// ---------------------------------------------------------------------------
// copy x -> h0  (float4, 1.6M threads)
// ---------------------------------------------------------------------------
__global__ void copy_x_kernel(const float* __restrict__ x) {
    int i = blockIdx.x * blockDim.x + threadIdx.x;
    if (i < NN * DD / 4) {
        reinterpret_cast<float4*>(g_h0)[i] = reinterpret_cast<const float4*>(x)[i];
    }
}

__global__ void zero_agg_kernel() {
    int i = blockIdx.x * blockDim.x + threadIdx.x;
    if (i < NN * DD / 4) {
        reinterpret_cast<float4*>(g_agg)[i] = make_float4(0.f, 0.f, 0.f, 0.f);
    }
}

// ---------------------------------------------------------------------------
// scatter: one warp per edge, each lane a float4 chunk of the 128-wide row
// ---------------------------------------------------------------------------
__global__ void scatter_kernel(const int* __restrict__ src,
                               const int* __restrict__ dst,
                               int cur) {
    int t = blockIdx.x * blockDim.x + threadIdx.x;
    if (t >= NE * 32) return;
    int e = t >> 5;
    int c = (t & 31) << 2;           // float offset within row (0,4,...,124)
    const float* __restrict__ H = cur ? g_h1 : g_h0;
    int s = src[e];
    int d = dst[e];
    float4 v = *reinterpret_cast<const float4*>(&H[s * DD + c]);
    float* a = &g_agg[d * DD + c];
    atomicAdd(a + 0, v.x);
    atomicAdd(a + 1, v.y);
    atomicAdd(a + 2, v.z);
    atomicAdd(a + 3, v.w);
}

// ---------------------------------------------------------------------------
// fused layer GEMM:
//   out = relu( (agg * deg_inv) @ Wl + h @ Wr + bl )
// as a single GEMM with K=256: A = [aggN | h], B = [Wl ; Wr].
// Tile: BM=64, BN=128, BK=32. 256 threads, 8x4 micro-tile per thread.
// ---------------------------------------------------------------------------
__global__ void sage_gemm_kernel(const float* __restrict__ Wl,
                                 const float* __restrict__ Wr,
                                 const float* __restrict__ bl,
                                 int layer, int cur) {
    const float* __restrict__ WlL = Wl + layer * DD * DD;
    const float* __restrict__ WrL = Wr + layer * DD * DD;
    const float* __restrict__ blL = bl + layer * DD;
    const float* __restrict__ H = cur ? g_h1 : g_h0;
    float* __restrict__ O = cur ? g_h0 : g_h1;

    __shared__ float As[64][32];
    __shared__ float Bs[32][128];
    __shared__ float sInv[64];

    const int m0 = blockIdx.x * 64;
    const int tid = threadIdx.x;
    const int rowbase = (tid >> 5) * 8;   // 0,8,...,56
    const int col = (tid & 31) * 4;       // 0,4,...,124

    if (tid < 64) {
        int m = m0 + tid;
        float dg = (m < NN) ? g_deg[m] : 1.0f;
        sInv[tid] = 1.0f / fmaxf(dg, 1.0f);
    }
    __syncthreads();

    float acc[8][4];
#pragma unroll
    for (int i = 0; i < 8; i++)
#pragma unroll
        for (int j = 0; j < 4; j++) acc[i][j] = 0.0f;

    for (int kk = 0; kk < 2 * DD; kk += 32) {
        // Load A tile: 64x32 = 2048 elems, 8 per thread
#pragma unroll
        for (int t = 0; t < 8; t++) {
            int idx = tid + t * 256;
            int m = idx >> 5;
            int k = idx & 31;
            int gm = m0 + m;
            int gk = kk + k;
            float v = 0.0f;
            if (gm < NN) {
                if (gk < DD)
                    v = g_agg[gm * DD + gk] * sInv[m];
                else
                    v = H[gm * DD + (gk - DD)];
            }
            As[m][k] = v;
        }
        // Load B tile: 32x128 = 4096 elems, 16 per thread
#pragma unroll
        for (int t = 0; t < 16; t++) {
            int idx = tid + t * 256;
            int k = idx >> 7;
            int n = idx & 127;
            int gk = kk + k;
            Bs[k][n] = (gk < DD) ? WlL[gk * DD + n] : WrL[(gk - DD) * DD + n];
        }
        __syncthreads();

#pragma unroll
        for (int k = 0; k < 32; k++) {
            float4 b4 = *reinterpret_cast<const float4*>(&Bs[k][col]);
            float a[8];
#pragma unroll
            for (int i = 0; i < 8; i++) a[i] = As[rowbase + i][k];
#pragma unroll
            for (int i = 0; i < 8; i++) {
                acc[i][0] = fmaf(a[i], b4.x, acc[i][0]);
                acc[i][1] = fmaf(a[i], b4.y, acc[i][1]);
                acc[i][2] = fmaf(a[i], b4.z, acc[i][2]);
                acc[i][3] = fmaf(a[i], b4.w, acc[i][3]);
            }
        }
        __syncthreads();
    }

    float4 bb = *reinterpret_cast<const float4*>(&blL[col]);
#pragma unroll
    for (int i = 0; i < 8; i++) {
        int gm = m0 + rowbase + i;
        if (gm < NN) {
            float4 v;
            v.x = fmaxf(acc[i][0] + bb.x, 0.0f);
            v.y = fmaxf(acc[i][1] + bb.y, 0.0f);
            v.z = fmaxf(acc[i][2] + bb.z, 0.0f);
            v.w = fmaxf(acc[i][3] + bb.w, 0.0f);
            *reinterpret_cast<float4*>(&O[gm * DD + col]) = v;
        }
    }
}

// ---------------------------------------------------------------------------
// final FC: out[m, 0:2] = h[m, :] @ fc_W + fc_b.  One warp per row.
// ---------------------------------------------------------------------------
__global__ void fc_kernel(const float* __restrict__ fcW,
                          const float* __restrict__ fcb,
                          float* __restrict__ out) {
    int w = (blockIdx.x * blockDim.x + threadIdx.x) >> 5;
    int lane = threadIdx.x & 31;
    if (w >= NN) return;
    const float* __restrict__ H = g_h0;  // after 6 layers (even), result is in h0
    float4 v = *reinterpret_cast<const float4*>(&H[w * DD + lane * 4]);
    int k0 = lane * 4;
    float s0 = v.x * fcW[(k0 + 0) * 2 + 0] + v.y * fcW[(k0 + 1) * 2 + 0] +
               v.z * fcW[(k0 + 2) * 2 + 0] + v.w * fcW[(k0 + 3) * 2 + 0];
    float s1 = v.x * fcW[(k0 + 0) * 2 + 1] + v.y * fcW[(k0 + 1) * 2 + 1] +
               v.z * fcW[(k0 + 2) * 2 + 1] + v.w * fcW[(k0 + 3) * 2 + 1];
#pragma unroll
    for (int o = 16; o > 0; o >>= 1) {
        s0 += __shfl_xor_sync(0xFFFFFFFFu, s0, o);
        s1 += __shfl_xor_sync(0xFFFFFFFFu, s1, o);
    }
    if (lane == 0) {
        out[w * 2 + 0] = s0 + fcb[0];
        out[w * 2 + 1] = s1 + fcb[1];
    }
}

// ---------------------------------------------------------------------------
// launch
// ---------------------------------------------------------------------------
extern "C" void kernel_launch(void* const* d_in, const int* in_sizes, int n_in,
                              void* d_out, int out_size) {
    const float* x   = (const float*)d_in[0];
    const int* ei    = (const int*)d_in[1];
    const float* Wl  = (const float*)d_in[2];
    const float* Wr  = (const float*)d_in[3];
    const float* bl  = (const float*)d_in[4];
    const float* fcW = (const float*)d_in[5];
    const float* fcb = (const float*)d_in[6];
    float* out = (float*)d_out;

    const int* src = ei;
    const int* dst = ei + NE;

    zero_deg_kernel<<<(NN + 255) / 256, 256>>>();
    deg_kernel<<<(NE + 255) / 256, 256>>>(dst);
    copy_x_kernel<<<(NN * DD / 4 + 255) / 256, 256>>>(x);

    int cur = 0;
    for (int layer = 0; layer < NL; layer++) {
        zero_agg_kernel<<<(NN * DD / 4 + 255) / 256, 256>>>();
        scatter_kernel<<<(NE * 32 + 255) / 256, 256>>>(src, dst, cur);
        sage_gemm_kernel<<<(NN + 63) / 64, 256>>>(Wl, Wr, bl, layer, cur);
        cur ^= 1;
    }

    fc_kernel<<<(NN * 32 + 255) / 256, 256>>>(fcW, fcb, out);
}

// round 6
// speedup vs baseline: 2.9823x; 2.9823x over previous
#include <cuda_runtime.h>
#include <cuda_bf16.h>

#define NN 50000
#define NE 600000
#define DD 128
#define NL 6

// Scratch buffers (no allocation allowed).
__device__ float g_h0[NN * DD];
__device__ float g_h1[NN * DD];
__device__ float g_agg[NN * DD];     // normalized mean-aggregate
__device__ int   g_deg[NN];
__device__ int   g_off[NN + 1];
__device__ int   g_cursor[NN];
__device__ int   g_csrc[NE];         // CSR (by dst) source indices

// ---------------------------------------------------------------------------
// CSR build
// ---------------------------------------------------------------------------
__global__ void zero_int_kernel() {
    int i = blockIdx.x * blockDim.x + threadIdx.x;
    if (i < NN) { g_deg[i] = 0; g_cursor[i] = 0; }
}

__global__ void deg_kernel(const int* __restrict__ dst) {
    int e = blockIdx.x * blockDim.x + threadIdx.x;
    if (e < NE) atomicAdd(&g_deg[dst[e]], 1);
}

// single-block exclusive scan over g_deg -> g_off
__global__ void scan_kernel() {
    __shared__ int part[256];
    const int tid = threadIdx.x;
    const int chunk = (NN + 255) / 256;
    const int start = tid * chunk;
    const int end = min(start + chunk, NN);
    int s = 0;
    for (int i = start; i < end; i++) s += g_deg[i];
    part[tid] = s;
    __syncthreads();
    if (tid == 0) {
        int acc = 0;
        for (int j = 0; j < 256; j++) { int t = part[j]; part[j] = acc; acc += t; }
    }
    __syncthreads();
    int acc = part[tid];
    for (int i = start; i < end; i++) { g_off[i] = acc; acc += g_deg[i]; }
    if (tid == 0) g_off[NN] = NE;
}

__global__ void fill_csr_kernel(const int* __restrict__ src,
                                const int* __restrict__ dst) {
    int e = blockIdx.x * blockDim.x + threadIdx.x;
    if (e >= NE) return;
    int d = dst[e];
    int p = atomicAdd(&g_cursor[d], 1);
    g_csrc[g_off[d] + p] = src[e];
}

// ---------------------------------------------------------------------------
// copy x -> h0
// ---------------------------------------------------------------------------
__global__ void copy_x_kernel(const float* __restrict__ x) {
    int i = blockIdx.x * blockDim.x + threadIdx.x;
    if (i < NN * DD / 4)
        reinterpret_cast<float4*>(g_h0)[i] = reinterpret_cast<const float4*>(x)[i];
}

// ---------------------------------------------------------------------------
// aggregation: one warp per node, gather-sum over CSR, fused 1/deg normalize
// ---------------------------------------------------------------------------
__global__ void aggregate_kernel(int cur) {
    int w = (blockIdx.x * blockDim.x + threadIdx.x) >> 5;
    if (w >= NN) return;
    int lane = threadIdx.x & 31;
    const float* __restrict__ H = cur ? g_h1 : g_h0;
    int beg = g_off[w];
    int end = g_off[w + 1];
    float4 acc = make_float4(0.f, 0.f, 0.f, 0.f);
    for (int p = beg; p < end; p++) {
        int s = g_csrc[p];  // broadcast load across the warp
        float4 v = *reinterpret_cast<const float4*>(&H[s * DD + lane * 4]);
        acc.x += v.x; acc.y += v.y; acc.z += v.z; acc.w += v.w;
    }
    float inv = 1.0f / fmaxf((float)(end - beg), 1.0f);
    acc.x *= inv; acc.y *= inv; acc.z *= inv; acc.w *= inv;
    *reinterpret_cast<float4*>(&g_agg[w * DD + lane * 4]) = acc;
}

// ---------------------------------------------------------------------------
// fused layer GEMM: out = relu( agg @ Wl + h @ Wr + bl )
// single GEMM, K=256: A = [agg | h], B = [Wl ; Wr].
// BM=128, BN=128, BK=16, 256 threads, 8x8 micro-tile.
// ---------------------------------------------------------------------------
__global__ void __launch_bounds__(256, 2)
sage_gemm_kernel(const float* __restrict__ Wl,
                 const float* __restrict__ Wr,
                 const float* __restrict__ bl,
                 int layer, int cur) {
    const float* __restrict__ WlL = Wl + layer * DD * DD;
    const float* __restrict__ WrL = Wr + layer * DD * DD;
    const float* __restrict__ blL = bl + layer * DD;
    const float* __restrict__ H = cur ? g_h1 : g_h0;
    float* __restrict__ O = cur ? g_h0 : g_h1;

    __shared__ float As[16][132];   // padded to avoid bank conflicts
    __shared__ float Bs[16][128];

    const int m0 = blockIdx.x * 128;
    const int tid = threadIdx.x;
    const int ty = tid >> 4;          // 0..15
    const int tx = tid & 15;          // 0..15
    const int row0 = ty * 8;
    const int col0 = tx * 8;

    float acc[8][8];
#pragma unroll
    for (int i = 0; i < 8; i++)
#pragma unroll
        for (int j = 0; j < 8; j++) acc[i][j] = 0.0f;

    for (int kk = 0; kk < 2 * DD; kk += 16) {
        const float* __restrict__ Aptr = (kk < DD) ? g_agg : H;
        const int ka = kk & (DD - 1);
        const float* __restrict__ Bptr = (kk < DD) ? (WlL + kk * DD)
                                                   : (WrL + (kk - DD) * DD);

        // A tile: 128 rows x 16 cols = 512 float4 loads; transpose into As[k][m]
#pragma unroll
        for (int t = 0; t < 2; t++) {
            int idx = tid + t * 256;
            int m = idx >> 2;             // 0..127
            int c4 = idx & 3;             // which float4 of the 16-wide k strip
            int gm = m0 + m;
            float4 v = make_float4(0.f, 0.f, 0.f, 0.f);
            if (gm < NN)
                v = *reinterpret_cast<const float4*>(&Aptr[gm * DD + ka + c4 * 4]);
            int k = c4 * 4;
            As[k + 0][m] = v.x;
            As[k + 1][m] = v.y;
            As[k + 2][m] = v.z;
            As[k + 3][m] = v.w;
        }
        // B tile: 16 x 128 = 512 float4 loads, direct
#pragma unroll
        for (int t = 0; t < 2; t++) {
            int idx = tid + t * 256;
            int r = idx >> 5;             // 0..15
            int c4 = idx & 31;            // 0..31
            *reinterpret_cast<float4*>(&Bs[r][c4 * 4]) =
                *reinterpret_cast<const float4*>(&Bptr[r * DD + c4 * 4]);
        }
        __syncthreads();

#pragma unroll
        for (int k = 0; k < 16; k++) {
            float a[8], b[8];
            *reinterpret_cast<float4*>(&a[0]) = *reinterpret_cast<const float4*>(&As[k][row0]);
            *reinterpret_cast<float4*>(&a[4]) = *reinterpret_cast<const float4*>(&As[k][row0 + 4]);
            *reinterpret_cast<float4*>(&b[0]) = *reinterpret_cast<const float4*>(&Bs[k][col0]);
            *reinterpret_cast<float4*>(&b[4]) = *reinterpret_cast<const float4*>(&Bs[k][col0 + 4]);
#pragma unroll
            for (int i = 0; i < 8; i++)
#pragma unroll
                for (int j = 0; j < 8; j++)
                    acc[i][j] = fmaf(a[i], b[j], acc[i][j]);
        }
        __syncthreads();
    }

    float bias[8];
    *reinterpret_cast<float4*>(&bias[0]) = *reinterpret_cast<const float4*>(&blL[col0]);
    *reinterpret_cast<float4*>(&bias[4]) = *reinterpret_cast<const float4*>(&blL[col0 + 4]);

#pragma unroll
    for (int i = 0; i < 8; i++) {
        int gm = m0 + row0 + i;
        if (gm < NN) {
            float4 v0, v1;
            v0.x = fmaxf(acc[i][0] + bias[0], 0.0f);
            v0.y = fmaxf(acc[i][1] + bias[1], 0.0f);
            v0.z = fmaxf(acc[i][2] + bias[2], 0.0f);
            v0.w = fmaxf(acc[i][3] + bias[3], 0.0f);
            v1.x = fmaxf(acc[i][4] + bias[4], 0.0f);
            v1.y = fmaxf(acc[i][5] + bias[5], 0.0f);
            v1.z = fmaxf(acc[i][6] + bias[6], 0.0f);
            v1.w = fmaxf(acc[i][7] + bias[7], 0.0f);
            *reinterpret_cast<float4*>(&O[gm * DD + col0]) = v0;
            *reinterpret_cast<float4*>(&O[gm * DD + col0 + 4]) = v1;
        }
    }
}

// ---------------------------------------------------------------------------
// final FC: out[m, 0:2] = h[m, :] @ fc_W + fc_b.  One warp per row.
// ---------------------------------------------------------------------------
__global__ void fc_kernel(const float* __restrict__ fcW,
                          const float* __restrict__ fcb,
                          float* __restrict__ out) {
    int w = (blockIdx.x * blockDim.x + threadIdx.x) >> 5;
    int lane = threadIdx.x & 31;
    if (w >= NN) return;
    const float* __restrict__ H = g_h0;  // after 6 layers result is in h0
    float4 v = *reinterpret_cast<const float4*>(&H[w * DD + lane * 4]);
    int k0 = lane * 4;
    float s0 = v.x * fcW[(k0 + 0) * 2 + 0] + v.y * fcW[(k0 + 1) * 2 + 0] +
               v.z * fcW[(k0 + 2) * 2 + 0] + v.w * fcW[(k0 + 3) * 2 + 0];
    float s1 = v.x * fcW[(k0 + 0) * 2 + 1] + v.y * fcW[(k0 + 1) * 2 + 1] +
               v.z * fcW[(k0 + 2) * 2 + 1] + v.w * fcW[(k0 + 3) * 2 + 1];
#pragma unroll
    for (int o = 16; o > 0; o >>= 1) {
        s0 += __shfl_xor_sync(0xFFFFFFFFu, s0, o);
        s1 += __shfl_xor_sync(0xFFFFFFFFu, s1, o);
    }
    if (lane == 0) {
        out[w * 2 + 0] = s0 + fcb[0];
        out[w * 2 + 1] = s1 + fcb[1];
    }
}

// ---------------------------------------------------------------------------
// launch
// ---------------------------------------------------------------------------
extern "C" void kernel_launch(void* const* d_in, const int* in_sizes, int n_in,
                              void* d_out, int out_size) {
    const float* x   = (const float*)d_in[0];
    const int* ei    = (const int*)d_in[1];
    const float* Wl  = (const float*)d_in[2];
    const float* Wr  = (const float*)d_in[3];
    const float* bl  = (const float*)d_in[4];
    const float* fcW = (const float*)d_in[5];
    const float* fcb = (const float*)d_in[6];
    float* out = (float*)d_out;

    const int* src = ei;
    const int* dst = ei + NE;

    zero_int_kernel<<<(NN + 255) / 256, 256>>>();
    deg_kernel<<<(NE + 255) / 256, 256>>>(dst);
    scan_kernel<<<1, 256>>>();
    fill_csr_kernel<<<(NE + 255) / 256, 256>>>(src, dst);
    copy_x_kernel<<<(NN * DD / 4 + 255) / 256, 256>>>(x);

    int cur = 0;
    for (int layer = 0; layer < NL; layer++) {
        // one warp per node: NN*32 threads
        aggregate_kernel<<<(NN * 32 + 255) / 256, 256>>>(cur);
        sage_gemm_kernel<<<(NN + 127) / 128, 256>>>(Wl, Wr, bl, layer, cur);
        cur ^= 1;
    }

    fc_kernel<<<(NN * 32 + 255) / 256, 256>>>(fcW, fcb, out);
}

// round 16
// speedup vs baseline: 4.0101x; 1.3446x over previous
#include <cuda_runtime.h>
#include <cuda_bf16.h>
#include <cstdint>

#define NN 50000
#define NE 600000
#define DD 128
#define NL 6
#define NT ((NN + 127) / 128)   // 391 M-tiles

// ---------------------------------------------------------------------------
// Split-bf16 planes: value = hi + lo, each plane 128 bf16 per node row (256B).
// ---------------------------------------------------------------------------
__device__ __nv_bfloat16 g_h0h[NN * DD];
__device__ __nv_bfloat16 g_h0l[NN * DD];
__device__ __nv_bfloat16 g_h1h[NN * DD];
__device__ __nv_bfloat16 g_h1l[NN * DD];
__device__ __nv_bfloat16 g_ah[NN * DD];            // aggregate hi
__device__ __nv_bfloat16 g_al[NN * DD];            // aggregate lo
__device__ __nv_bfloat16 g_Wbh[NL * DD * 256];     // weights [n][k], K=256 (Wl|Wr), hi
__device__ __nv_bfloat16 g_Wbl[NL * DD * 256];     // lo
__device__ int g_deg[NN];
__device__ int g_off[NN + 1];
__device__ int g_cursor[NN];
__device__ int g_csrc[NE];

// ---------------------------------------------------------------------------
// PTX helpers (base-target only: ldmatrix + mma.sync)
// ---------------------------------------------------------------------------
__device__ __forceinline__ uint32_t smem_u32(const void* p) {
    uint32_t a;
    asm("{ .reg .u64 t; cvta.to.shared.u64 t, %1; cvt.u32.u64 %0, t; }" : "=r"(a) : "l"(p));
    return a;
}

#define LDSM4(r0, r1, r2, r3, addr) \
    asm volatile("ldmatrix.sync.aligned.m8n8.x4.shared.b16 {%0,%1,%2,%3}, [%4];" \
                 : "=r"(r0), "=r"(r1), "=r"(r2), "=r"(r3) : "r"(addr))

#define MMA_BF16(c, a, b) \
    asm volatile("mma.sync.aligned.m16n8k16.row.col.f32.bf16.bf16.f32 " \
                 "{%0,%1,%2,%3}, {%4,%5,%6,%7}, {%8,%9}, {%0,%1,%2,%3};" \
                 : "+f"((c)[0]), "+f"((c)[1]), "+f"((c)[2]), "+f"((c)[3]) \
                 : "r"((a)[0]), "r"((a)[1]), "r"((a)[2]), "r"((a)[3]), \
                   "r"((b)[0]), "r"((b)[1]))

// ---------------------------------------------------------------------------
// CSR build (unchanged)
// ---------------------------------------------------------------------------
__global__ void zero_int_kernel() {
    int i = blockIdx.x * blockDim.x + threadIdx.x;
    if (i < NN) { g_deg[i] = 0; g_cursor[i] = 0; }
}
__global__ void deg_kernel(const int* __restrict__ dst) {
    int e = blockIdx.x * blockDim.x + threadIdx.x;
    if (e < NE) atomicAdd(&g_deg[dst[e]], 1);
}
__global__ void scan_kernel() {
    __shared__ int part[256];
    const int tid = threadIdx.x;
    const int chunk = (NN + 255) / 256;
    const int start = tid * chunk;
    const int end = min(start + chunk, NN);
    int s = 0;
    for (int i = start; i < end; i++) s += g_deg[i];
    part[tid] = s;
    __syncthreads();
    if (tid == 0) {
        int acc = 0;
        for (int j = 0; j < 256; j++) { int t = part[j]; part[j] = acc; acc += t; }
    }
    __syncthreads();
    int acc = part[tid];
    for (int i = start; i < end; i++) { g_off[i] = acc; acc += g_deg[i]; }
    if (tid == 0) g_off[NN] = NE;
}
__global__ void fill_csr_kernel(const int* __restrict__ src, const int* __restrict__ dst) {
    int e = blockIdx.x * blockDim.x + threadIdx.x;
    if (e >= NE) return;
    int d = dst[e];
    int p = atomicAdd(&g_cursor[d], 1);
    g_csrc[g_off[d] + p] = src[e];
}

// ---------------------------------------------------------------------------
// split helpers
// ---------------------------------------------------------------------------
__device__ __forceinline__ void split2(float a, float b, uint32_t& hw, uint32_t& lw) {
    __nv_bfloat16 ha = __float2bfloat16(a);
    __nv_bfloat16 hb = __float2bfloat16(b);
    __nv_bfloat16 la = __float2bfloat16(a - __bfloat162float(ha));
    __nv_bfloat16 lb = __float2bfloat16(b - __bfloat162float(hb));
    __nv_bfloat162 h2; h2.x = ha; h2.y = hb;
    __nv_bfloat162 l2; l2.x = la; l2.y = lb;
    hw = *reinterpret_cast<uint32_t*>(&h2);
    lw = *reinterpret_cast<uint32_t*>(&l2);
}

// x -> split planes h0.  One thread per 4 features.
__global__ void split_x_kernel(const float* __restrict__ x) {
    int q = blockIdx.x * blockDim.x + threadIdx.x;
    if (q >= NN * 32) return;
    int node = q >> 5;
    int f0 = (q & 31) * 4;
    float4 v = *reinterpret_cast<const float4*>(&x[node * DD + f0]);
    uint32_t hw0, lw0, hw1, lw1;
    split2(v.x, v.y, hw0, lw0);
    split2(v.z, v.w, hw1, lw1);
    *reinterpret_cast<uint2*>(&g_h0h[node * DD + f0]) = make_uint2(hw0, hw1);
    *reinterpret_cast<uint2*>(&g_h0l[node * DD + f0]) = make_uint2(lw0, lw1);
}

// Wl/Wr -> [n][k] split planes.  One thread per (layer, k, n).
__global__ void prepack_w_kernel(const float* __restrict__ Wl, const float* __restrict__ Wr) {
    int idx = blockIdx.x * blockDim.x + threadIdx.x;
    if (idx >= NL * 256 * DD) return;
    int layer = idx / (256 * DD);
    int r = idx - layer * 256 * DD;
    int k = r >> 7;
    int n = r & 127;
    float w = (k < DD) ? Wl[layer * DD * DD + k * DD + n]
                       : Wr[layer * DD * DD + (k - DD) * DD + n];
    __nv_bfloat16 hi = __float2bfloat16(w);
    __nv_bfloat16 lo = __float2bfloat16(w - __bfloat162float(hi));
    int base = (layer * DD + n) * 256 + k;
    g_Wbh[base] = hi;
    g_Wbl[base] = lo;
}

// ---------------------------------------------------------------------------
// aggregation: warp per node, gather-sum from split planes, normalize, split
// ---------------------------------------------------------------------------
__global__ void aggregate_kernel(int cur) {
    int w = (blockIdx.x * blockDim.x + threadIdx.x) >> 5;
    if (w >= NN) return;
    int lane = threadIdx.x & 31;
    const __nv_bfloat16* __restrict__ Hh = cur ? g_h1h : g_h0h;
    const __nv_bfloat16* __restrict__ Hl = cur ? g_h1l : g_h0l;
    int f0 = lane * 4;
    int beg = g_off[w];
    int end = g_off[w + 1];
    float a0 = 0.f, a1 = 0.f, a2 = 0.f, a3 = 0.f;
    for (int p = beg; p < end; p++) {
        int s = g_csrc[p];
        uint2 hv = *reinterpret_cast<const uint2*>(&Hh[s * DD + f0]);
        uint2 lv = *reinterpret_cast<const uint2*>(&Hl[s * DD + f0]);
        float2 h0 = __bfloat1622float2(*reinterpret_cast<__nv_bfloat162*>(&hv.x));
        float2 h1 = __bfloat1622float2(*reinterpret_cast<__nv_bfloat162*>(&hv.y));
        float2 l0 = __bfloat1622float2(*reinterpret_cast<__nv_bfloat162*>(&lv.x));
        float2 l1 = __bfloat1622float2(*reinterpret_cast<__nv_bfloat162*>(&lv.y));
        a0 += h0.x + l0.x;
        a1 += h0.y + l0.y;
        a2 += h1.x + l1.x;
        a3 += h1.y + l1.y;
    }
    float inv = 1.0f / fmaxf((float)(end - beg), 1.0f);
    uint32_t hw0, lw0, hw1, lw1;
    split2(a0 * inv, a1 * inv, hw0, lw0);
    split2(a2 * inv, a3 * inv, hw1, lw1);
    *reinterpret_cast<uint2*>(&g_ah[w * DD + f0]) = make_uint2(hw0, hw1);
    *reinterpret_cast<uint2*>(&g_al[w * DD + f0]) = make_uint2(lw0, lw1);
}

// ---------------------------------------------------------------------------
// mma.sync split-bf16 layer GEMM:
//   out = relu( [agg|h] @ [Wl;Wr] + bl ),  D = Ahi*Bhi + Ahi*Blo + Alo*Bhi
// CTA tile 128x128, 8 warps (4x2), warp tile 32x64.  K=256 in 4 chunks of 64.
// smem rows padded to 144 B (conflict-free ldmatrix: 144 mod 128 = 16).
// ---------------------------------------------------------------------------
#define ASTB 144                    // smem row stride (bytes) for 64 bf16 rows
#define SA_HI 0
#define SA_LO (128 * ASTB)          // 18432
#define SB_HI (2 * 128 * ASTB)      // 36864
#define SB_LO (3 * 128 * ASTB)      // 55296
#define SBIAS (4 * 128 * ASTB)      // 73728
#define SM_TOT (SBIAS + 512)        // 74240

__global__ void __launch_bounds__(256)
sage_mma_kernel(const float* __restrict__ bl, int layer, int cur) {
    extern __shared__ char smem[];
    const uint32_t sb = smem_u32(smem);
    const int tid = threadIdx.x;
    const int wid = tid >> 5;
    const int lane = tid & 31;
    const int m0 = blockIdx.x * 128;
    const int wr = wid & 3;         // m-offset wr*32
    const int wc = wid >> 2;        // n-offset wc*64

    const __nv_bfloat16* __restrict__ Hh = cur ? g_h1h : g_h0h;
    const __nv_bfloat16* __restrict__ Hl = cur ? g_h1l : g_h0l;
    __nv_bfloat16* __restrict__ Oh = cur ? g_h0h : g_h1h;
    __nv_bfloat16* __restrict__ Ol = cur ? g_h0l : g_h1l;

    if (tid < 128)
        *reinterpret_cast<float*>(smem + SBIAS + tid * 4) = bl[layer * DD + tid];

    // ldmatrix per-thread address selectors
    const int lq = lane >> 3;       // 0..3
    const int lr = lane & 7;        // 0..7
    const int aRow = (lq & 1) * 8 + lr;    // matrix row select
    const int aColH = (lq >> 1) * 8;       // k-half select
    const int bNRow = (lq >> 1) * 8 + lr;
    const int bColH = (lq & 1) * 8;

    float acc[2][8][4];
#pragma unroll
    for (int m = 0; m < 2; m++)
#pragma unroll
        for (int n = 0; n < 8; n++)
#pragma unroll
            for (int j = 0; j < 4; j++) acc[m][n][j] = 0.0f;

    for (int c = 0; c < 4; c++) {
        const __nv_bfloat16* __restrict__ Ah = (c < 2) ? g_ah : Hh;
        const __nv_bfloat16* __restrict__ Al = (c < 2) ? g_al : Hl;
        const int k0g = (c & 1) * 64;

        // fill A planes: 128 rows x 64 bf16 = 128 rows x 8 uint4 = 1024 uint4/plane
#pragma unroll
        for (int it = 0; it < 4; it++) {
            int idx = tid + it * 256;     // 0..1023
            int row = idx >> 3;           // 0..127
            int u = idx & 7;              // 0..7 (16B chunk within 128B row)
            int gm = m0 + row;
            uint4 vh = make_uint4(0u, 0u, 0u, 0u);
            uint4 vl = make_uint4(0u, 0u, 0u, 0u);
            if (gm < NN) {
                vh = *reinterpret_cast<const uint4*>(&Ah[gm * DD + k0g + u * 8]);
                vl = *reinterpret_cast<const uint4*>(&Al[gm * DD + k0g + u * 8]);
            }
            *reinterpret_cast<uint4*>(smem + SA_HI + row * ASTB + u * 16) = vh;
            *reinterpret_cast<uint4*>(smem + SA_LO + row * ASTB + u * 16) = vl;
        }
        // fill B planes: 128 n-rows x 64 bf16 = 1024 uint4/plane
#pragma unroll
        for (int it = 0; it < 4; it++) {
            int idx = tid + it * 256;
            int row = idx >> 3;
            int u = idx & 7;
            int gb = (layer * DD + row) * 256 + c * 64 + u * 8;
            *reinterpret_cast<uint4*>(smem + SB_HI + row * ASTB + u * 16) =
                *reinterpret_cast<const uint4*>(&g_Wbh[gb]);
            *reinterpret_cast<uint4*>(smem + SB_LO + row * ASTB + u * 16) =
                *reinterpret_cast<const uint4*>(&g_Wbl[gb]);
        }
        __syncthreads();

#pragma unroll
        for (int kk = 0; kk < 4; kk++) {
            const int k0 = kk * 16;
            uint32_t ah[2][4], al[2][4];
#pragma unroll
            for (int m = 0; m < 2; m++) {
                uint32_t addr = sb + (uint32_t)((wr * 32 + m * 16 + aRow) * ASTB +
                                                (k0 + aColH) * 2);
                LDSM4(ah[m][0], ah[m][1], ah[m][2], ah[m][3], addr + SA_HI);
                LDSM4(al[m][0], al[m][1], al[m][2], al[m][3], addr + SA_LO);
            }
            uint32_t bh[8][2], blo[8][2];
#pragma unroll
            for (int nb = 0; nb < 4; nb++) {
                uint32_t addr = sb + (uint32_t)((wc * 64 + nb * 16 + bNRow) * ASTB +
                                                (k0 + bColH) * 2);
                LDSM4(bh[2 * nb][0], bh[2 * nb][1], bh[2 * nb + 1][0], bh[2 * nb + 1][1],
                      addr + SB_HI);
                LDSM4(blo[2 * nb][0], blo[2 * nb][1], blo[2 * nb + 1][0], blo[2 * nb + 1][1],
                      addr + SB_LO);
            }
#pragma unroll
            for (int m = 0; m < 2; m++)
#pragma unroll
                for (int n = 0; n < 8; n++) {
                    MMA_BF16(acc[m][n], ah[m], bh[n]);   // hi*hi
                    MMA_BF16(acc[m][n], ah[m], blo[n]);  // hi*lo
                    MMA_BF16(acc[m][n], al[m], bh[n]);   // lo*hi
                }
        }
        __syncthreads();
    }

    // epilogue: bias + relu + split, write hi/lo planes
    const float* bias = reinterpret_cast<const float*>(smem + SBIAS);
#pragma unroll
    for (int m = 0; m < 2; m++) {
        int g0 = m0 + wr * 32 + m * 16 + (lane >> 2);
#pragma unroll
        for (int n = 0; n < 8; n++) {
            int colb = wc * 64 + n * 8 + 2 * (lane & 3);
            float b0 = bias[colb], b1 = bias[colb + 1];
            if (g0 < NN) {
                float v0 = fmaxf(acc[m][n][0] + b0, 0.0f);
                float v1 = fmaxf(acc[m][n][1] + b1, 0.0f);
                uint32_t hw, lw;
                split2(v0, v1, hw, lw);
                *reinterpret_cast<uint32_t*>(&Oh[g0 * DD + colb]) = hw;
                *reinterpret_cast<uint32_t*>(&Ol[g0 * DD + colb]) = lw;
            }
            int g1 = g0 + 8;
            if (g1 < NN) {
                float v0 = fmaxf(acc[m][n][2] + b0, 0.0f);
                float v1 = fmaxf(acc[m][n][3] + b1, 0.0f);
                uint32_t hw, lw;
                split2(v0, v1, hw, lw);
                *reinterpret_cast<uint32_t*>(&Oh[g1 * DD + colb]) = hw;
                *reinterpret_cast<uint32_t*>(&Ol[g1 * DD + colb]) = lw;
            }
        }
    }
}

// ---------------------------------------------------------------------------
// final FC from split planes:  out[m, 0:2] = (hi+lo) @ fc_W + fc_b
// ---------------------------------------------------------------------------
__global__ void fc_kernel(const float* __restrict__ fcW, const float* __restrict__ fcb,
                          float* __restrict__ out) {
    int w = (blockIdx.x * blockDim.x + threadIdx.x) >> 5;
    int lane = threadIdx.x & 31;
    if (w >= NN) return;
    int f0 = lane * 4;
    uint2 hv = *reinterpret_cast<const uint2*>(&g_h0h[w * DD + f0]);  // after 6 layers
    uint2 lv = *reinterpret_cast<const uint2*>(&g_h0l[w * DD + f0]);
    float2 h0 = __bfloat1622float2(*reinterpret_cast<__nv_bfloat162*>(&hv.x));
    float2 h1 = __bfloat1622float2(*reinterpret_cast<__nv_bfloat162*>(&hv.y));
    float2 l0 = __bfloat1622float2(*reinterpret_cast<__nv_bfloat162*>(&lv.x));
    float2 l1 = __bfloat1622float2(*reinterpret_cast<__nv_bfloat162*>(&lv.y));
    float v0 = h0.x + l0.x, v1 = h0.y + l0.y, v2 = h1.x + l1.x, v3 = h1.y + l1.y;
    float s0 = v0 * fcW[(f0 + 0) * 2 + 0] + v1 * fcW[(f0 + 1) * 2 + 0] +
               v2 * fcW[(f0 + 2) * 2 + 0] + v3 * fcW[(f0 + 3) * 2 + 0];
    float s1 = v0 * fcW[(f0 + 0) * 2 + 1] + v1 * fcW[(f0 + 1) * 2 + 1] +
               v2 * fcW[(f0 + 2) * 2 + 1] + v3 * fcW[(f0 + 3) * 2 + 1];
#pragma unroll
    for (int o = 16; o > 0; o >>= 1) {
        s0 += __shfl_xor_sync(0xFFFFFFFFu, s0, o);
        s1 += __shfl_xor_sync(0xFFFFFFFFu, s1, o);
    }
    if (lane == 0) {
        out[w * 2 + 0] = s0 + fcb[0];
        out[w * 2 + 1] = s1 + fcb[1];
    }
}

// ---------------------------------------------------------------------------
// launch
// ---------------------------------------------------------------------------
extern "C" void kernel_launch(void* const* d_in, const int* in_sizes, int n_in,
                              void* d_out, int out_size) {
    const float* x   = (const float*)d_in[0];
    const int* ei    = (const int*)d_in[1];
    const float* Wl  = (const float*)d_in[2];
    const float* Wr  = (const float*)d_in[3];
    const float* bl  = (const float*)d_in[4];
    const float* fcW = (const float*)d_in[5];
    const float* fcb = (const float*)d_in[6];
    float* out = (float*)d_out;

    const int* src = ei;
    const int* dst = ei + NE;

    cudaFuncSetAttribute(sage_mma_kernel,
                         cudaFuncAttributeMaxDynamicSharedMemorySize, SM_TOT);

    zero_int_kernel<<<(NN + 255) / 256, 256>>>();
    deg_kernel<<<(NE + 255) / 256, 256>>>(dst);
    scan_kernel<<<1, 256>>>();
    fill_csr_kernel<<<(NE + 255) / 256, 256>>>(src, dst);
    split_x_kernel<<<(NN * 32 + 255) / 256, 256>>>(x);
    prepack_w_kernel<<<(NL * 256 * DD + 255) / 256, 256>>>(Wl, Wr);

    int cur = 0;
    for (int layer = 0; layer < NL; layer++) {
        aggregate_kernel<<<(NN * 32 + 255) / 256, 256>>>(cur);
        sage_mma_kernel<<<NT, 256, SM_TOT>>>(bl, layer, cur);
        cur ^= 1;
    }

    fc_kernel<<<(NN * 32 + 255) / 256, 256>>>(fcW, fcb, out);
}